// round 1
// baseline (speedup 1.0000x reference)
#include <cuda_runtime.h>

#define S 32
#define NMAX 204800
#define MMAX 2048
#define NBMAX 256

// ---------------- scratch (no allocations allowed) ----------------
__device__ float2 g_xy[NMAX];
__device__ int    g_flags[NMAX];
__device__ int    g_rankl[NMAX];
__device__ int    g_bsum[NBMAX];
__device__ int    g_boff[NBMAX];
__device__ int    g_sidx[MMAX * S];
__device__ int    g_scount[MMAX];

// ---------------- K0: pack xy + clear flags ----------------
__global__ void k_pack(const float* __restrict__ pts, int N) {
    int i = blockIdx.x * blockDim.x + threadIdx.x;
    if (i < N) {
        g_xy[i] = make_float2(pts[i * 5 + 0], pts[i * 5 + 1]);
        g_flags[i] = 0;
    }
}

// ---------------- K1: per-box first-32 in-radius (+ fill) ----------------
// One block (256 thr) per box. Ordered chunked scan, 8 points/thread/chunk.
__global__ void __launch_bounds__(256) k_sample(const float* __restrict__ boxes, int N) {
    int m = blockIdx.x;
    float bx = boxes[m * 7 + 0];
    float by = boxes[m * 7 + 1];
    float hx = __fmul_rn(boxes[m * 7 + 3], 0.5f);
    float hy = __fmul_rn(boxes[m * 7 + 4], 0.5f);
    float r  = __fmul_rn(sqrtf(__fadd_rn(__fmul_rn(hx, hx), __fmul_rn(hy, hy))), 1.1f);

    __shared__ int s_m[S], s_u[S];
    __shared__ int s_mc, s_uc;
    __shared__ int w_m[8], w_u[8];
    if (threadIdx.x == 0) { s_mc = 0; s_uc = 0; }
    __syncthreads();

    const int lane = threadIdx.x & 31;
    const int wid  = threadIdx.x >> 5;
    const float4* xy4 = reinterpret_cast<const float4*>(g_xy);

    for (int base = 0; base < N; base += 256 * 8) {
        int i0 = base + threadIdx.x * 8;
        // unconditional vector loads (g_xy padded to NMAX; garbage masked below)
        float2 p[8];
        #pragma unroll
        for (int k = 0; k < 4; k++) {
            float4 v = xy4[(i0 >> 1) + k];
            p[2 * k + 0] = make_float2(v.x, v.y);
            p[2 * k + 1] = make_float2(v.z, v.w);
        }
        unsigned mbits = 0, vbits = 0;
        #pragma unroll
        for (int k = 0; k < 8; k++) {
            int i = i0 + k;
            if (i < N) {
                vbits |= (1u << k);
                float dx = __fadd_rn(bx, -p[k].x);
                float dy = __fadd_rn(by, -p[k].y);
                float d2 = __fadd_rn(__fmul_rn(dx, dx), __fmul_rn(dy, dy));
                if (sqrtf(d2) <= r) mbits |= (1u << k);
            }
        }
        unsigned ubits = vbits & ~mbits;
        int mloc = __popc(mbits), uloc = __popc(ubits);

        // warp inclusive scans
        int im = mloc, iu = uloc;
        #pragma unroll
        for (int off = 1; off < 32; off <<= 1) {
            int vm = __shfl_up_sync(0xffffffffu, im, off);
            int vu = __shfl_up_sync(0xffffffffu, iu, off);
            if (lane >= off) { im += vm; iu += vu; }
        }
        int em = im - mloc, eu = iu - uloc;
        if (lane == 31) { w_m[wid] = im; w_u[wid] = iu; }
        __syncthreads();

        int mo = 0, uo = 0;
        #pragma unroll
        for (int w = 0; w < 8; w++) {
            if (w < wid) { mo += w_m[w]; uo += w_u[w]; }
        }
        int mpos = s_mc + mo + em;
        int upos = s_uc + uo + eu;
        #pragma unroll
        for (int k = 0; k < 8; k++) {
            if (mbits & (1u << k)) { if (mpos < S) s_m[mpos] = i0 + k; mpos++; }
            else if (ubits & (1u << k)) { if (upos < S) s_u[upos] = i0 + k; upos++; }
        }
        __syncthreads();
        if (threadIdx.x == 0) {
            int tm = 0, tu = 0;
            #pragma unroll
            for (int w = 0; w < 8; w++) { tm += w_m[w]; tu += w_u[w]; }
            s_mc += tm; s_uc += tu;
        }
        __syncthreads();
        if (s_mc >= S && s_uc >= S) break;
    }

    int c = (s_mc < S) ? s_mc : S;
    if (threadIdx.x == 0) g_scount[m] = c;
    if (threadIdx.x < S) {
        int j = threadIdx.x;
        int v = (j < c) ? s_m[j] : s_u[j - c];
        g_sidx[m * S + j] = v;
        g_flags[v] = 1;   // benign race: all writers store 1
    }
}

// ---------------- K2a: per-1024-block exclusive scan of flags ----------------
__global__ void __launch_bounds__(1024) k_scan_local(int N) {
    int i = blockIdx.x * 1024 + threadIdx.x;
    int f = (i < N) ? g_flags[i] : 0;
    __shared__ int wsum[32];
    int lane = threadIdx.x & 31, wid = threadIdx.x >> 5;
    int inc = f;
    #pragma unroll
    for (int off = 1; off < 32; off <<= 1) {
        int v = __shfl_up_sync(0xffffffffu, inc, off);
        if (lane >= off) inc += v;
    }
    int exc = inc - f;
    if (lane == 31) wsum[wid] = inc;
    __syncthreads();
    if (wid == 0) {
        int v = wsum[lane];
        int iv = v;
        #pragma unroll
        for (int off = 1; off < 32; off <<= 1) {
            int t = __shfl_up_sync(0xffffffffu, iv, off);
            if (lane >= off) iv += t;
        }
        wsum[lane] = iv - v;   // exclusive warp offsets
    }
    __syncthreads();
    int off = wsum[wid];
    if (i < N) g_rankl[i] = exc + off;
    if (threadIdx.x == 1023) g_bsum[blockIdx.x] = inc + off;  // block total
}

// ---------------- K2b: scan block sums (NB <= 256) ----------------
__global__ void __launch_bounds__(256) k_scan_b(int NB) {
    int t = threadIdx.x;
    int v = (t < NB) ? g_bsum[t] : 0;
    __shared__ int wsum[8];
    int lane = t & 31, wid = t >> 5;
    int inc = v;
    #pragma unroll
    for (int off = 1; off < 32; off <<= 1) {
        int x = __shfl_up_sync(0xffffffffu, inc, off);
        if (lane >= off) inc += x;
    }
    if (lane == 31) wsum[wid] = inc;
    __syncthreads();
    int o = 0;
    #pragma unroll
    for (int w = 0; w < 8; w++) if (w < wid) o += wsum[w];
    g_boff[t] = inc - v + o;   // exclusive
}

__device__ __forceinline__ int g_rank(int n) { return g_rankl[n] + g_boff[n >> 10]; }

// ---------------- K3a: init query_points rows with points[0] ----------------
__global__ void k_init_qp(const float* __restrict__ pts, float* __restrict__ qp, int total) {
    int t = blockIdx.x * blockDim.x + threadIdx.x;
    if (t < total) qp[t] = pts[t % 5];
}

// ---------------- K3b: scatter flagged points by rank ----------------
__global__ void k_scatter(const float* __restrict__ pts, float* __restrict__ qp, int N) {
    int n = blockIdx.x * blockDim.x + threadIdx.x;
    if (n < N && g_flags[n]) {
        int r = g_rank(n);
        #pragma unroll
        for (int c = 0; c < 5; c++) qp[r * 5 + c] = pts[n * 5 + c];
    }
}

// ---------------- K4: sampled_points + idx ----------------
__global__ void k_out(const float* __restrict__ pts, float* __restrict__ outp,
                      float* __restrict__ outi, int M) {
    int t = blockIdx.x * blockDim.x + threadIdx.x;
    if (t < M * S) {
        int m = t / S, j = t - m * S;
        int c = g_scount[m];
        int p = g_sidx[t];
        bool msk = (j < c);
        outi[t] = msk ? (float)g_rank(p) : 0.0f;
        #pragma unroll
        for (int cc = 0; cc < 5; cc++)
            outp[t * 5 + cc] = msk ? pts[p * 5 + cc] : 0.0f;
    }
}

// ---------------- launch ----------------
extern "C" void kernel_launch(void* const* d_in, const int* in_sizes, int n_in,
                              void* d_out, int out_size) {
    const float* pts   = (const float*)d_in[0];
    const float* boxes = (const float*)d_in[1];
    int N = in_sizes[0] / 5;
    int M = in_sizes[1] / 7;
    if (N > NMAX) N = NMAX;
    if (M > MMAX) M = MMAX;

    float* out  = (float*)d_out;
    float* outp = out;                            // sampled_points [M*S*5]
    float* outi = out + (size_t)M * S * 5;        // idx            [M*S]
    float* qp   = outi + (size_t)M * S;           // query_points   [M*S*5]

    int NB = (N + 1023) / 1024;

    k_pack<<<(N + 255) / 256, 256>>>(pts, N);
    k_sample<<<M, 256>>>(boxes, N);
    k_scan_local<<<NB, 1024>>>(N);
    k_scan_b<<<1, 256>>>(NB);
    k_init_qp<<<(M * S * 5 + 255) / 256, 256>>>(pts, qp, M * S * 5);
    k_scatter<<<(N + 255) / 256, 256>>>(pts, qp, N);
    k_out<<<(M * S + 255) / 256, 256>>>(pts, outp, outi, M);
}

// round 2
// speedup vs baseline: 3.8760x; 3.8760x over previous
#include <cuda_runtime.h>

#define S 32
#define NMAX 204800
#define MMAX 2048
#define NBMAX 256

#define GX 38
#define NC (GX * GX)
#define CELL 4.0f
#define ORG (-76.0f)
#define HITCAP 2048

// ---------------- scratch (no allocations allowed) ----------------
__device__ float2 g_xy[NMAX];
__device__ int    g_flags[NMAX];
__device__ int    g_rankl[NMAX];
__device__ int    g_bsum[NBMAX];
__device__ int    g_boff[NBMAX];
__device__ int    g_sidx[MMAX * S];
__device__ int    g_scount[MMAX];
// grid
__device__ int    g_cell[NMAX];
__device__ int    g_chist[NC];
__device__ int    g_ccur[NC];
__device__ int    g_cstart[NC + 2];
__device__ float2 g_cxy[NMAX];
__device__ int    g_cidx[NMAX];

__device__ __forceinline__ int cellc(float v) {
    int c = (int)floorf((v - ORG) * (1.0f / CELL));
    return min(max(c, 0), GX - 1);
}

// ---------------- K0a: zero grid counters ----------------
__global__ void k_zero() {
    int i = blockIdx.x * blockDim.x + threadIdx.x;
    if (i < NC) { g_chist[i] = 0; g_ccur[i] = 0; }
}

// ---------------- K0b: pack xy, clear flags, histogram cells ----------------
__global__ void k_pack(const float* __restrict__ pts, int N) {
    int i = blockIdx.x * blockDim.x + threadIdx.x;
    if (i < N) {
        float x = pts[i * 5 + 0], y = pts[i * 5 + 1];
        g_xy[i] = make_float2(x, y);
        g_flags[i] = 0;
        int cell = cellc(y) * GX + cellc(x);
        g_cell[i] = cell;
        atomicAdd(&g_chist[cell], 1);
    }
}

// ---------------- K0c: exclusive prefix over cell histogram (1 block) ----------------
__global__ void __launch_bounds__(1024) k_prefix(int N) {
    __shared__ int wofs[32];
    int tid = threadIdx.x, lane = tid & 31, wid = tid >> 5;
    int a = (2 * tid     < NC) ? g_chist[2 * tid]     : 0;
    int b = (2 * tid + 1 < NC) ? g_chist[2 * tid + 1] : 0;
    int s = a + b;
    int inc = s;
    #pragma unroll
    for (int off = 1; off < 32; off <<= 1) {
        int v = __shfl_up_sync(0xffffffffu, inc, off);
        if (lane >= off) inc += v;
    }
    if (lane == 31) wofs[wid] = inc;
    __syncthreads();
    if (wid == 0) {
        int v = wofs[lane];
        int iv = v;
        #pragma unroll
        for (int off = 1; off < 32; off <<= 1) {
            int t = __shfl_up_sync(0xffffffffu, iv, off);
            if (lane >= off) iv += t;
        }
        wofs[lane] = iv - v;
    }
    __syncthreads();
    int exc = inc - s + wofs[wid];       // exclusive over thread-pair sums
    if (2 * tid     <= NC + 1) g_cstart[2 * tid]     = exc;
    if (2 * tid + 1 <= NC + 1) g_cstart[2 * tid + 1] = exc + a;
    for (int i = tid; i < NC; i += 1024) g_ccur[i] = 0;
}

// ---------------- K0d: scatter points into cell lists ----------------
__global__ void k_fill_cells(int N) {
    int i = blockIdx.x * blockDim.x + threadIdx.x;
    if (i < N) {
        int cell = g_cell[i];
        int pos = g_cstart[cell] + atomicAdd(&g_ccur[cell], 1);
        g_cxy[pos] = g_xy[i];
        g_cidx[pos] = i;
    }
}

// ---------------- K1: per-box selection via grid ----------------
__global__ void __launch_bounds__(256) k_boxes(const float* __restrict__ boxes, int N) {
    int m = blockIdx.x;
    int tid = threadIdx.x;
    float bx = boxes[m * 7 + 0];
    float by = boxes[m * 7 + 1];
    float hx = __fmul_rn(boxes[m * 7 + 3], 0.5f);
    float hy = __fmul_rn(boxes[m * 7 + 4], 0.5f);
    float r  = __fmul_rn(sqrtf(__fadd_rn(__fmul_rn(hx, hx), __fmul_rn(hy, hy))), 1.1f);

    __shared__ int s_hit[HITCAP];
    __shared__ int s_cnt, s_c;
    __shared__ int s_m[S], s_u[S];
    if (tid == 0) s_cnt = 0;
    __syncthreads();

    int cx0 = cellc(bx - r - 0.5f), cx1 = cellc(bx + r + 0.5f);
    int cy0 = cellc(by - r - 0.5f), cy1 = cellc(by + r + 0.5f);

    for (int cy = cy0; cy <= cy1; cy++) {
        int s0 = g_cstart[cy * GX + cx0];
        int s1 = g_cstart[cy * GX + cx1 + 1];
        for (int i = s0 + tid; i < s1; i += 256) {
            float2 p = g_cxy[i];
            float dx = __fadd_rn(bx, -p.x);
            float dy = __fadd_rn(by, -p.y);
            float d2 = __fadd_rn(__fmul_rn(dx, dx), __fmul_rn(dy, dy));
            if (sqrtf(d2) <= r) {
                int pos = atomicAdd(&s_cnt, 1);
                if (pos < HITCAP) s_hit[pos] = g_cidx[i];
            }
        }
    }
    __syncthreads();
    int cnt = s_cnt;

    if (cnt <= HITCAP) {
        // pad to pow2 and bitonic sort ascending; keep 32 smallest
        int P = 32;
        while (P < cnt) P <<= 1;
        for (int i = tid; i < P; i += 256) if (i >= cnt) s_hit[i] = 0x7fffffff;
        __syncthreads();
        for (int k = 2; k <= P; k <<= 1) {
            for (int j = k >> 1; j > 0; j >>= 1) {
                for (int i = tid; i < P; i += 256) {
                    int ixj = i ^ j;
                    if (ixj > i) {
                        int a = s_hit[i], b = s_hit[ixj];
                        bool up = ((i & k) == 0);
                        if ((a > b) == up) { s_hit[i] = b; s_hit[ixj] = a; }
                    }
                }
                __syncthreads();
            }
        }
        int c = min(cnt, S);
        if (tid < c) s_m[tid] = s_hit[tid];
        if (tid == 0) s_c = c;
    } else {
        // overflow fallback: ordered warp scan for first 32 in-radius
        if (tid < 32) {
            int lane = tid;
            int got = 0;
            for (int base = 0; got < S && base < N; base += 32) {
                int i = base + lane;
                bool mem = false;
                if (i < N) {
                    float2 p = g_xy[i];
                    float dx = __fadd_rn(bx, -p.x);
                    float dy = __fadd_rn(by, -p.y);
                    float d2 = __fadd_rn(__fmul_rn(dx, dx), __fmul_rn(dy, dy));
                    mem = (sqrtf(d2) <= r);
                }
                unsigned bmask = __ballot_sync(0xffffffffu, mem);
                int before = __popc(bmask & ((1u << lane) - 1));
                if (mem && got + before < S) s_m[got + before] = i;
                got += __popc(bmask);
            }
            if (lane == 0) s_c = S;
        }
    }
    __syncthreads();
    int c = s_c;

    if (c < S) {
        // fill with first (32-c) OUT-of-radius indices ascending (warp 0)
        if (tid < 32) {
            int lane = tid;
            int need = S - c;
            int got = 0;
            for (int base = 0; got < need && base < N; base += 32) {
                int i = base + lane;
                bool nm = false;
                if (i < N) {
                    float2 p = g_xy[i];
                    float dx = __fadd_rn(bx, -p.x);
                    float dy = __fadd_rn(by, -p.y);
                    float d2 = __fadd_rn(__fmul_rn(dx, dx), __fmul_rn(dy, dy));
                    nm = !(sqrtf(d2) <= r);
                }
                unsigned bmask = __ballot_sync(0xffffffffu, nm);
                int before = __popc(bmask & ((1u << lane) - 1));
                if (nm && got + before < need) s_u[got + before] = i;
                got += __popc(bmask);
            }
        }
        __syncthreads();
    }

    if (tid < S) {
        int v = (tid < c) ? s_m[tid] : s_u[tid - c];
        g_sidx[m * S + tid] = v;
        g_flags[v] = 1;    // benign race: all writers store 1
    }
    if (tid == 0) g_scount[m] = c;
}

// ---------------- K2a: per-1024-block exclusive scan of flags ----------------
__global__ void __launch_bounds__(1024) k_scan_local(int N) {
    int i = blockIdx.x * 1024 + threadIdx.x;
    int f = (i < N) ? g_flags[i] : 0;
    __shared__ int wsum[32];
    int lane = threadIdx.x & 31, wid = threadIdx.x >> 5;
    int inc = f;
    #pragma unroll
    for (int off = 1; off < 32; off <<= 1) {
        int v = __shfl_up_sync(0xffffffffu, inc, off);
        if (lane >= off) inc += v;
    }
    int exc = inc - f;
    if (lane == 31) wsum[wid] = inc;
    __syncthreads();
    if (wid == 0) {
        int v = wsum[lane];
        int iv = v;
        #pragma unroll
        for (int off = 1; off < 32; off <<= 1) {
            int t = __shfl_up_sync(0xffffffffu, iv, off);
            if (lane >= off) iv += t;
        }
        wsum[lane] = iv - v;
    }
    __syncthreads();
    int off = wsum[wid];
    if (i < N) g_rankl[i] = exc + off;
    if (threadIdx.x == 1023) g_bsum[blockIdx.x] = inc + off;
}

// ---------------- K2b: scan block sums ----------------
__global__ void __launch_bounds__(256) k_scan_b(int NB) {
    int t = threadIdx.x;
    int v = (t < NB) ? g_bsum[t] : 0;
    __shared__ int wsum[8];
    int lane = t & 31, wid = t >> 5;
    int inc = v;
    #pragma unroll
    for (int off = 1; off < 32; off <<= 1) {
        int x = __shfl_up_sync(0xffffffffu, inc, off);
        if (lane >= off) inc += x;
    }
    if (lane == 31) wsum[wid] = inc;
    __syncthreads();
    int o = 0;
    #pragma unroll
    for (int w = 0; w < 8; w++) if (w < wid) o += wsum[w];
    g_boff[t] = inc - v + o;
}

__device__ __forceinline__ int g_rank(int n) { return g_rankl[n] + g_boff[n >> 10]; }

// ---------------- K3a: init query_points rows with points[0] ----------------
__global__ void k_init_qp(const float* __restrict__ pts, float* __restrict__ qp, int total) {
    int t = blockIdx.x * blockDim.x + threadIdx.x;
    if (t < total) qp[t] = pts[t % 5];
}

// ---------------- K3b: scatter flagged points by rank ----------------
__global__ void k_scatter(const float* __restrict__ pts, float* __restrict__ qp, int N) {
    int n = blockIdx.x * blockDim.x + threadIdx.x;
    if (n < N && g_flags[n]) {
        int r = g_rank(n);
        #pragma unroll
        for (int c = 0; c < 5; c++) qp[r * 5 + c] = pts[n * 5 + c];
    }
}

// ---------------- K4: sampled_points + idx ----------------
__global__ void k_out(const float* __restrict__ pts, float* __restrict__ outp,
                      float* __restrict__ outi, int M) {
    int t = blockIdx.x * blockDim.x + threadIdx.x;
    if (t < M * S) {
        int m = t / S, j = t - m * S;
        int c = g_scount[m];
        int p = g_sidx[t];
        bool msk = (j < c);
        outi[t] = msk ? (float)g_rank(p) : 0.0f;
        #pragma unroll
        for (int cc = 0; cc < 5; cc++)
            outp[t * 5 + cc] = msk ? pts[p * 5 + cc] : 0.0f;
    }
}

// ---------------- launch ----------------
extern "C" void kernel_launch(void* const* d_in, const int* in_sizes, int n_in,
                              void* d_out, int out_size) {
    const float* pts   = (const float*)d_in[0];
    const float* boxes = (const float*)d_in[1];
    int N = in_sizes[0] / 5;
    int M = in_sizes[1] / 7;
    if (N > NMAX) N = NMAX;
    if (M > MMAX) M = MMAX;

    float* out  = (float*)d_out;
    float* outp = out;                            // sampled_points [M*S*5]
    float* outi = out + (size_t)M * S * 5;        // idx            [M*S]
    float* qp   = outi + (size_t)M * S;           // query_points   [M*S*5]

    int NB = (N + 1023) / 1024;

    k_zero<<<(NC + 255) / 256, 256>>>();
    k_pack<<<(N + 255) / 256, 256>>>(pts, N);
    k_prefix<<<1, 1024>>>(N);
    k_fill_cells<<<(N + 255) / 256, 256>>>(N);
    k_boxes<<<M, 256>>>(boxes, N);
    k_scan_local<<<NB, 1024>>>(N);
    k_scan_b<<<1, 256>>>(NB);
    k_init_qp<<<(M * S * 5 + 255) / 256, 256>>>(pts, qp, M * S * 5);
    k_scatter<<<(N + 255) / 256, 256>>>(pts, qp, N);
    k_out<<<(M * S + 255) / 256, 256>>>(pts, outp, outi, M);
}

// round 4
// speedup vs baseline: 4.2913x; 1.1071x over previous
#include <cuda_runtime.h>

#define S 32
#define NMAX 204800
#define MMAX 2048

#define GX 38
#define NC (GX * GX)
#define CELL 4.0f
#define ORG (-76.0f)
#define HITCAP 2048
#define TILE 4096
#define NTMAX 64

// ---------------- scratch (no allocations allowed) ----------------
__device__ float2 g_xy[NMAX];
__device__ int    g_flags[NMAX];
__device__ int    g_rankl[NMAX];
__device__ int    g_sidx[MMAX * S];
__device__ int    g_scount[MMAX];
__device__ int    g_cell[NMAX];      // packed: cell | (rank<<11)
__device__ int    g_chist[NC];
__device__ int    g_cstart[NC + 2];
__device__ float2 g_cxy[NMAX];
__device__ int    g_cidx[NMAX];
__device__ unsigned long long g_tstate[NTMAX];  // lookback: (status<<32)|sum
__device__ int    g_total;

__device__ __forceinline__ int cellc(float v) {
    int c = (int)floorf((v - ORG) * (1.0f / CELL));
    return min(max(c, 0), GX - 1);
}

// ---------------- K0: zero counters + lookback states ----------------
__global__ void k_zero() {
    int i = blockIdx.x * blockDim.x + threadIdx.x;
    if (i < NC) g_chist[i] = 0;
    if (i < NTMAX) g_tstate[i] = 0ULL;
}

// ---------------- K1: pack xy, clear flags, hierarchical histogram ----------------
// 512 threads x 8 points. Shared-mem per-block hist, one global atomic per (block,cell).
__global__ void __launch_bounds__(512) k_pack(const float* __restrict__ pts, int N) {
    __shared__ int sh_cnt[NC];
    __shared__ int sh_base[NC];
    int t = threadIdx.x;
    for (int c = t; c < NC; c += 512) sh_cnt[c] = 0;
    __syncthreads();

    int i0 = (blockIdx.x * 512 + t) * 8;
    float2 P[8];
    int cell[8], lr[8];
    bool val[8];
    if (i0 + 8 <= N) {
        const float4* p4 = (const float4*)(pts + (size_t)i0 * 5);
        float4 v[10];
        #pragma unroll
        for (int k = 0; k < 10; k++) v[k] = p4[k];
        const float* f = (const float*)v;
        #pragma unroll
        for (int k = 0; k < 8; k++) { P[k] = make_float2(f[5 * k], f[5 * k + 1]); val[k] = true; }
    } else {
        #pragma unroll
        for (int k = 0; k < 8; k++) {
            int i = i0 + k;
            val[k] = (i < N);
            P[k] = val[k] ? make_float2(pts[i * 5], pts[i * 5 + 1]) : make_float2(0.f, 0.f);
        }
    }
    #pragma unroll
    for (int k = 0; k < 8; k++) {
        if (val[k]) {
            int i = i0 + k;
            g_xy[i] = P[k];
            g_flags[i] = 0;
            cell[k] = cellc(P[k].y) * GX + cellc(P[k].x);
            lr[k] = atomicAdd(&sh_cnt[cell[k]], 1);
        }
    }
    __syncthreads();
    for (int c = t; c < NC; c += 512) {
        int n = sh_cnt[c];
        sh_base[c] = n ? atomicAdd(&g_chist[c], n) : 0;
    }
    __syncthreads();
    #pragma unroll
    for (int k = 0; k < 8; k++)
        if (val[k]) g_cell[i0 + k] = cell[k] | ((sh_base[cell[k]] + lr[k]) << 11);
}

// ---------------- K2: exclusive prefix over cell histogram (1 block) ----------------
__global__ void __launch_bounds__(1024) k_prefix() {
    __shared__ int wofs[32];
    int tid = threadIdx.x, lane = tid & 31, wid = tid >> 5;
    int a = (2 * tid     < NC) ? g_chist[2 * tid]     : 0;
    int b = (2 * tid + 1 < NC) ? g_chist[2 * tid + 1] : 0;
    int s = a + b;
    int inc = s;
    #pragma unroll
    for (int off = 1; off < 32; off <<= 1) {
        int v = __shfl_up_sync(0xffffffffu, inc, off);
        if (lane >= off) inc += v;
    }
    if (lane == 31) wofs[wid] = inc;
    __syncthreads();
    if (wid == 0) {
        int v = wofs[lane];
        int iv = v;
        #pragma unroll
        for (int off = 1; off < 32; off <<= 1) {
            int t2 = __shfl_up_sync(0xffffffffu, iv, off);
            if (lane >= off) iv += t2;
        }
        wofs[lane] = iv - v;
    }
    __syncthreads();
    int exc = inc - s + wofs[wid];
    if (2 * tid     <= NC + 1) g_cstart[2 * tid]     = exc;
    if (2 * tid + 1 <= NC + 1) g_cstart[2 * tid + 1] = exc + a;
}

// ---------------- K3: atomic-free scatter into cell lists ----------------
__global__ void __launch_bounds__(256) k_fill(int N) {
    int q = (blockIdx.x * 256 + threadIdx.x) * 4;
    if (q >= N) return;
    if (q + 4 <= N) {
        int4 pc = *(const int4*)&g_cell[q];
        float4 a = *(const float4*)&g_xy[q];
        float4 b = *(const float4*)&g_xy[q + 2];
        int c0 = pc.x & 2047, c1 = pc.y & 2047, c2 = pc.z & 2047, c3 = pc.w & 2047;
        int p0 = g_cstart[c0] + (pc.x >> 11);
        int p1 = g_cstart[c1] + (pc.y >> 11);
        int p2 = g_cstart[c2] + (pc.z >> 11);
        int p3 = g_cstart[c3] + (pc.w >> 11);
        g_cxy[p0] = make_float2(a.x, a.y); g_cidx[p0] = q;
        g_cxy[p1] = make_float2(a.z, a.w); g_cidx[p1] = q + 1;
        g_cxy[p2] = make_float2(b.x, b.y); g_cidx[p2] = q + 2;
        g_cxy[p3] = make_float2(b.z, b.w); g_cidx[p3] = q + 3;
    } else {
        for (int k = 0; k < 4 && q + k < N; k++) {
            int pc = g_cell[q + k];
            int pos = g_cstart[pc & 2047] + (pc >> 11);
            g_cxy[pos] = g_xy[q + k];
            g_cidx[pos] = q + k;
        }
    }
}

// ---------------- K4: per-box selection via grid ----------------
__global__ void __launch_bounds__(256) k_boxes(const float* __restrict__ boxes, int N) {
    int m = blockIdx.x;
    int tid = threadIdx.x;
    float bx = boxes[m * 7 + 0];
    float by = boxes[m * 7 + 1];
    float hx = __fmul_rn(boxes[m * 7 + 3], 0.5f);
    float hy = __fmul_rn(boxes[m * 7 + 4], 0.5f);
    float r  = __fmul_rn(sqrtf(__fadd_rn(__fmul_rn(hx, hx), __fmul_rn(hy, hy))), 1.1f);

    __shared__ int s_hit[HITCAP];
    __shared__ int s_cnt, s_c;
    __shared__ int s_m[S], s_u[S];
    if (tid == 0) s_cnt = 0;
    __syncthreads();

    int cx0 = cellc(bx - r - 0.5f), cx1 = cellc(bx + r + 0.5f);
    int cy0 = cellc(by - r - 0.5f), cy1 = cellc(by + r + 0.5f);

    for (int cy = cy0; cy <= cy1; cy++) {
        int s0 = g_cstart[cy * GX + cx0];
        int s1 = g_cstart[cy * GX + cx1 + 1];
        for (int i = s0 + tid; i < s1; i += 256) {
            float2 p = g_cxy[i];
            float dx = __fadd_rn(bx, -p.x);
            float dy = __fadd_rn(by, -p.y);
            float d2 = __fadd_rn(__fmul_rn(dx, dx), __fmul_rn(dy, dy));
            if (sqrtf(d2) <= r) {
                int pos = atomicAdd(&s_cnt, 1);
                if (pos < HITCAP) s_hit[pos] = g_cidx[i];
            }
        }
    }
    __syncthreads();
    int cnt = s_cnt;

    if (cnt <= HITCAP) {
        int P = 32;
        while (P < cnt) P <<= 1;
        for (int i = tid; i < P; i += 256) if (i >= cnt) s_hit[i] = 0x7fffffff;
        __syncthreads();
        for (int k = 2; k <= P; k <<= 1) {
            for (int j = k >> 1; j > 0; j >>= 1) {
                for (int i = tid; i < P; i += 256) {
                    int ixj = i ^ j;
                    if (ixj > i) {
                        int a = s_hit[i], b = s_hit[ixj];
                        bool up = ((i & k) == 0);
                        if ((a > b) == up) { s_hit[i] = b; s_hit[ixj] = a; }
                    }
                }
                __syncthreads();
            }
        }
        int c = min(cnt, S);
        if (tid < c) s_m[tid] = s_hit[tid];
        if (tid == 0) s_c = c;
    } else {
        if (tid < 32) {
            int lane = tid;
            int got = 0;
            for (int base = 0; got < S && base < N; base += 32) {
                int i = base + lane;
                bool mem = false;
                if (i < N) {
                    float2 p = g_xy[i];
                    float dx = __fadd_rn(bx, -p.x);
                    float dy = __fadd_rn(by, -p.y);
                    float d2 = __fadd_rn(__fmul_rn(dx, dx), __fmul_rn(dy, dy));
                    mem = (sqrtf(d2) <= r);
                }
                unsigned bmask = __ballot_sync(0xffffffffu, mem);
                int before = __popc(bmask & ((1u << lane) - 1));
                if (mem && got + before < S) s_m[got + before] = i;
                got += __popc(bmask);
            }
            if (lane == 0) s_c = S;
        }
    }
    __syncthreads();
    int c = s_c;

    if (c < S) {
        if (tid < 32) {
            int lane = tid;
            int need = S - c;
            int got = 0;
            for (int base = 0; got < need && base < N; base += 32) {
                int i = base + lane;
                bool nm = false;
                if (i < N) {
                    float2 p = g_xy[i];
                    float dx = __fadd_rn(bx, -p.x);
                    float dy = __fadd_rn(by, -p.y);
                    float d2 = __fadd_rn(__fmul_rn(dx, dx), __fmul_rn(dy, dy));
                    nm = !(sqrtf(d2) <= r);
                }
                unsigned bmask = __ballot_sync(0xffffffffu, nm);
                int before = __popc(bmask & ((1u << lane) - 1));
                if (nm && got + before < need) s_u[got + before] = i;
                got += __popc(bmask);
            }
        }
        __syncthreads();
    }

    if (tid < S) {
        int v = (tid < c) ? s_m[tid] : s_u[tid - c];
        g_sidx[m * S + tid] = v;
        g_flags[v] = 1;   // benign race: all writers store 1
    }
    if (tid == 0) g_scount[m] = c;
}

// ---------------- K5: single-pass rank scan (decoupled lookback) + qp scatter ----------------
__global__ void __launch_bounds__(512) k_scan(const float* __restrict__ pts,
                                              float* __restrict__ qp, int N) {
    __shared__ int wsums[16];
    __shared__ int s_total;
    __shared__ int s_off;
    int bid = blockIdx.x, t = threadIdx.x, lane = t & 31, wid = t >> 5;
    int i0 = bid * TILE + t * 8;

    int fl[8];
    {   // g_flags beyond N is never written (stays zero from module init); masked anyway
        const int4* fp = (const int4*)&g_flags[i0];
        int4 a = fp[0], b = fp[1];
        fl[0] = a.x; fl[1] = a.y; fl[2] = a.z; fl[3] = a.w;
        fl[4] = b.x; fl[5] = b.y; fl[6] = b.z; fl[7] = b.w;
    }
    int tsum = 0;
    #pragma unroll
    for (int k = 0; k < 8; k++) { if (i0 + k >= N) fl[k] = 0; tsum += fl[k]; }

    int inc = tsum;
    #pragma unroll
    for (int off = 1; off < 32; off <<= 1) {
        int v = __shfl_up_sync(0xffffffffu, inc, off);
        if (lane >= off) inc += v;
    }
    int exc = inc - tsum;
    if (lane == 31) wsums[wid] = inc;
    __syncthreads();
    if (wid == 0) {
        int v = (lane < 16) ? wsums[lane] : 0;
        int iv = v;
        #pragma unroll
        for (int off = 1; off < 32; off <<= 1) {
            int x = __shfl_up_sync(0xffffffffu, iv, off);
            if (lane >= off) iv += x;
        }
        if (lane == 15) s_total = iv;
        if (lane < 16) wsums[lane] = iv - v;
    }
    __syncthreads();
    int texc = exc + wsums[wid];

    if (t == 0) {
        int total = s_total;
        long long off = 0;
        if (bid > 0) {
            atomicExch(&g_tstate[bid], (1ULL << 32) | (unsigned)total);  // aggregate
            int j = bid - 1;
            while (1) {
                unsigned long long s;
                do { s = atomicAdd(&g_tstate[j], 0ULL); } while (!(s >> 32));
                off += (unsigned)s;
                if ((s >> 32) == 2ULL) break;
                j--;
            }
        }
        atomicExch(&g_tstate[bid], (2ULL << 32) | (unsigned)(off + total));  // inclusive
        s_off = (int)off;
        if (bid == (int)gridDim.x - 1) g_total = (int)off + total;
    }
    __syncthreads();

    int run = s_off + texc;
    #pragma unroll
    for (int k = 0; k < 8; k++) {
        int i = i0 + k;
        if (i < N) {
            g_rankl[i] = run;
            if (fl[k]) {
                const float* src = pts + (size_t)i * 5;
                float* dst = qp + (size_t)run * 5;
                dst[0] = src[0]; dst[1] = src[1]; dst[2] = src[2];
                dst[3] = src[3]; dst[4] = src[4];
                run++;
            }
        }
    }
}

// ---------------- K6: sampled_points + idx + qp padding ----------------
__global__ void k_out(const float* __restrict__ pts, float* __restrict__ outp,
                      float* __restrict__ outi, float* __restrict__ qp, int M) {
    int t = blockIdx.x * blockDim.x + threadIdx.x;
    if (t < M * S) {
        int m = t >> 5, j = t & 31;
        int c = g_scount[m];
        int p = g_sidx[t];
        bool msk = (j < c);
        outi[t] = msk ? (float)g_rankl[p] : 0.0f;
        #pragma unroll
        for (int cc = 0; cc < 5; cc++)
            outp[t * 5 + cc] = msk ? pts[p * 5 + cc] : 0.0f;
        if (t >= g_total) {
            #pragma unroll
            for (int cc = 0; cc < 5; cc++) qp[t * 5 + cc] = pts[cc];
        }
    }
}

// ---------------- launch ----------------
extern "C" void kernel_launch(void* const* d_in, const int* in_sizes, int n_in,
                              void* d_out, int out_size) {
    const float* pts   = (const float*)d_in[0];
    const float* boxes = (const float*)d_in[1];
    int N = in_sizes[0] / 5;
    int M = in_sizes[1] / 7;
    if (N > NMAX) N = NMAX;
    if (M > MMAX) M = MMAX;

    float* out  = (float*)d_out;
    float* outp = out;                            // sampled_points [M*S*5]
    float* outi = out + (size_t)M * S * 5;        // idx            [M*S]
    float* qp   = outi + (size_t)M * S;           // query_points   [M*S*5]

    int NT = (N + TILE - 1) / TILE;

    k_zero<<<(NC + 255) / 256, 256>>>();
    k_pack<<<(N + 4095) / 4096, 512>>>(pts, N);
    k_prefix<<<1, 1024>>>();
    k_fill<<<(N + 1023) / 1024, 256>>>(N);
    k_boxes<<<M, 256>>>(boxes, N);
    k_scan<<<NT, 512>>>(pts, qp, N);
    k_out<<<(M * S + 255) / 256, 256>>>(pts, outp, outi, qp, M);
}

// round 5
// speedup vs baseline: 5.2065x; 1.2133x over previous
#include <cuda_runtime.h>

#define S 32
#define NMAX 204800
#define MMAX 2048

#define GX 38
#define NC (GX * GX)
#define CELL 4.0f
#define ORG (-76.0f)
#define HITCAP 2048
#define TILE 2048
#define NTMAX 128

// ---------------- scratch (no allocations allowed) ----------------
__device__ float2 g_xy[NMAX];
__device__ int    g_flags[NMAX];
__device__ int    g_rankl[NMAX];
__device__ int    g_sidx[MMAX * S];
__device__ int    g_scount[MMAX];
__device__ int    g_cell[NMAX];      // packed: cell | (rank<<11)
__device__ int    g_chist[NC];
__device__ int    g_cstart[NC + 2];
__device__ float2 g_cxy[NMAX];
__device__ int    g_cidx[NMAX];
__device__ unsigned long long g_tstate[NTMAX];  // lookback: (status<<32)|sum
__device__ int    g_total;

__device__ __forceinline__ int cellc(float v) {
    int c = (int)floorf((v - ORG) * (1.0f / CELL));
    return min(max(c, 0), GX - 1);
}

// ---------------- K1: pack xy, clear flags, hierarchical histogram ----------------
// 256 threads x 4 points. Shared-mem per-block hist, one global atomic per (block,cell).
__global__ void __launch_bounds__(256) k_pack(const float* __restrict__ pts, int N) {
    __shared__ int sh_cnt[NC];
    __shared__ int sh_base[NC];
    int t = threadIdx.x;
    for (int c = t; c < NC; c += 256) sh_cnt[c] = 0;
    __syncthreads();

    int i0 = (blockIdx.x * 256 + t) * 4;
    float2 P[4];
    int cell[4], lr[4];
    bool val[4];
    if (i0 + 4 <= N) {
        const float4* p4 = (const float4*)(pts + (size_t)i0 * 5);
        float4 v[5];
        #pragma unroll
        for (int k = 0; k < 5; k++) v[k] = p4[k];
        const float* f = (const float*)v;
        #pragma unroll
        for (int k = 0; k < 4; k++) { P[k] = make_float2(f[5 * k], f[5 * k + 1]); val[k] = true; }
    } else {
        #pragma unroll
        for (int k = 0; k < 4; k++) {
            int i = i0 + k;
            val[k] = (i < N);
            P[k] = val[k] ? make_float2(pts[i * 5], pts[i * 5 + 1]) : make_float2(0.f, 0.f);
        }
    }
    #pragma unroll
    for (int k = 0; k < 4; k++) {
        if (val[k]) {
            int i = i0 + k;
            g_xy[i] = P[k];
            g_flags[i] = 0;
            cell[k] = cellc(P[k].y) * GX + cellc(P[k].x);
            lr[k] = atomicAdd(&sh_cnt[cell[k]], 1);
        }
    }
    __syncthreads();
    for (int c = t; c < NC; c += 256) {
        int n = sh_cnt[c];
        sh_base[c] = n ? atomicAdd(&g_chist[c], n) : 0;
    }
    __syncthreads();
    #pragma unroll
    for (int k = 0; k < 4; k++)
        if (val[k]) g_cell[i0 + k] = cell[k] | ((sh_base[cell[k]] + lr[k]) << 11);
}

// ---------------- K2: exclusive prefix over cell histogram (1 block) + reset hist ----------------
__global__ void __launch_bounds__(1024) k_prefix() {
    __shared__ int wofs[32];
    int tid = threadIdx.x, lane = tid & 31, wid = tid >> 5;
    int a = 0, b = 0;
    if (2 * tid < NC)     { a = g_chist[2 * tid];     g_chist[2 * tid] = 0; }
    if (2 * tid + 1 < NC) { b = g_chist[2 * tid + 1]; g_chist[2 * tid + 1] = 0; }
    int s = a + b;
    int inc = s;
    #pragma unroll
    for (int off = 1; off < 32; off <<= 1) {
        int v = __shfl_up_sync(0xffffffffu, inc, off);
        if (lane >= off) inc += v;
    }
    if (lane == 31) wofs[wid] = inc;
    __syncthreads();
    if (wid == 0) {
        int v = wofs[lane];
        int iv = v;
        #pragma unroll
        for (int off = 1; off < 32; off <<= 1) {
            int t2 = __shfl_up_sync(0xffffffffu, iv, off);
            if (lane >= off) iv += t2;
        }
        wofs[lane] = iv - v;
    }
    __syncthreads();
    int exc = inc - s + wofs[wid];
    if (2 * tid     <= NC + 1) g_cstart[2 * tid]     = exc;
    if (2 * tid + 1 <= NC + 1) g_cstart[2 * tid + 1] = exc + a;
}

// ---------------- K3: atomic-free scatter into cell lists (1 pt/thread) ----------------
__global__ void __launch_bounds__(256) k_fill(int N) {
    int i = blockIdx.x * 256 + threadIdx.x;
    if (i < N) {
        int pc = g_cell[i];
        int pos = g_cstart[pc & 2047] + (pc >> 11);
        g_cxy[pos] = g_xy[i];
        g_cidx[pos] = i;
    }
}

// ---------------- K4: per-box selection via grid ----------------
__global__ void __launch_bounds__(256) k_boxes(const float* __restrict__ boxes, int N) {
    int m = blockIdx.x;
    int tid = threadIdx.x;
    float bx = boxes[m * 7 + 0];
    float by = boxes[m * 7 + 1];
    float hx = __fmul_rn(boxes[m * 7 + 3], 0.5f);
    float hy = __fmul_rn(boxes[m * 7 + 4], 0.5f);
    float r  = __fmul_rn(sqrtf(__fadd_rn(__fmul_rn(hx, hx), __fmul_rn(hy, hy))), 1.1f);

    __shared__ int s_hit[HITCAP];
    __shared__ int s_cnt, s_c;
    __shared__ int s_m[S], s_u[S];
    if (tid == 0) s_cnt = 0;
    __syncthreads();

    int cx0 = cellc(bx - r - 0.5f), cx1 = cellc(bx + r + 0.5f);
    int cy0 = cellc(by - r - 0.5f), cy1 = cellc(by + r + 0.5f);

    for (int cy = cy0; cy <= cy1; cy++) {
        int s0 = g_cstart[cy * GX + cx0];
        int s1 = g_cstart[cy * GX + cx1 + 1];
        for (int i = s0 + tid; i < s1; i += 256) {
            float2 p = g_cxy[i];
            float dx = __fadd_rn(bx, -p.x);
            float dy = __fadd_rn(by, -p.y);
            float d2 = __fadd_rn(__fmul_rn(dx, dx), __fmul_rn(dy, dy));
            if (sqrtf(d2) <= r) {
                int pos = atomicAdd(&s_cnt, 1);
                if (pos < HITCAP) s_hit[pos] = g_cidx[i];
            }
        }
    }
    __syncthreads();
    int cnt = s_cnt;

    if (cnt <= HITCAP) {
        int P = 32;
        while (P < cnt) P <<= 1;
        for (int i = tid; i < P; i += 256) if (i >= cnt) s_hit[i] = 0x7fffffff;
        __syncthreads();
        for (int k = 2; k <= P; k <<= 1) {
            for (int j = k >> 1; j > 0; j >>= 1) {
                for (int i = tid; i < P; i += 256) {
                    int ixj = i ^ j;
                    if (ixj > i) {
                        int a = s_hit[i], b = s_hit[ixj];
                        bool up = ((i & k) == 0);
                        if ((a > b) == up) { s_hit[i] = b; s_hit[ixj] = a; }
                    }
                }
                __syncthreads();
            }
        }
        int c = min(cnt, S);
        if (tid < c) s_m[tid] = s_hit[tid];
        if (tid == 0) s_c = c;
    } else {
        if (tid < 32) {
            int lane = tid;
            int got = 0;
            for (int base = 0; got < S && base < N; base += 32) {
                int i = base + lane;
                bool mem = false;
                if (i < N) {
                    float2 p = g_xy[i];
                    float dx = __fadd_rn(bx, -p.x);
                    float dy = __fadd_rn(by, -p.y);
                    float d2 = __fadd_rn(__fmul_rn(dx, dx), __fmul_rn(dy, dy));
                    mem = (sqrtf(d2) <= r);
                }
                unsigned bmask = __ballot_sync(0xffffffffu, mem);
                int before = __popc(bmask & ((1u << lane) - 1));
                if (mem && got + before < S) s_m[got + before] = i;
                got += __popc(bmask);
            }
            if (lane == 0) s_c = S;
        }
    }
    __syncthreads();
    int c = s_c;

    if (c < S) {
        if (tid < 32) {
            int lane = tid;
            int need = S - c;
            int got = 0;
            for (int base = 0; got < need && base < N; base += 32) {
                int i = base + lane;
                bool nm = false;
                if (i < N) {
                    float2 p = g_xy[i];
                    float dx = __fadd_rn(bx, -p.x);
                    float dy = __fadd_rn(by, -p.y);
                    float d2 = __fadd_rn(__fmul_rn(dx, dx), __fmul_rn(dy, dy));
                    nm = !(sqrtf(d2) <= r);
                }
                unsigned bmask = __ballot_sync(0xffffffffu, nm);
                int before = __popc(bmask & ((1u << lane) - 1));
                if (nm && got + before < need) s_u[got + before] = i;
                got += __popc(bmask);
            }
        }
        __syncthreads();
    }

    if (tid < S) {
        int v = (tid < c) ? s_m[tid] : s_u[tid - c];
        g_sidx[m * S + tid] = v;
        g_flags[v] = 1;   // benign race: all writers store 1
    }
    if (tid == 0) g_scount[m] = c;
}

// ---------------- K5: single-pass rank scan (warp-parallel lookback) + qp scatter ----------------
__global__ void __launch_bounds__(256) k_scan(const float* __restrict__ pts,
                                              float* __restrict__ qp, int N) {
    __shared__ int wsums[8];
    __shared__ int s_total;
    __shared__ int s_off;
    int bid = blockIdx.x, t = threadIdx.x, lane = t & 31, wid = t >> 5;
    int i0 = bid * TILE + t * 8;

    int fl[8];
    {   // g_flags beyond N is never set (cleared by k_pack only for i<N; >=N stays 0); masked anyway
        const int4* fp = (const int4*)&g_flags[i0];
        int4 a = fp[0], b = fp[1];
        fl[0] = a.x; fl[1] = a.y; fl[2] = a.z; fl[3] = a.w;
        fl[4] = b.x; fl[5] = b.y; fl[6] = b.z; fl[7] = b.w;
    }
    int tsum = 0;
    #pragma unroll
    for (int k = 0; k < 8; k++) { if (i0 + k >= N) fl[k] = 0; tsum += fl[k]; }

    int inc = tsum;
    #pragma unroll
    for (int off = 1; off < 32; off <<= 1) {
        int v = __shfl_up_sync(0xffffffffu, inc, off);
        if (lane >= off) inc += v;
    }
    int exc = inc - tsum;
    if (lane == 31) wsums[wid] = inc;
    __syncthreads();
    if (wid == 0) {
        int v = (lane < 8) ? wsums[lane] : 0;
        int iv = v;
        #pragma unroll
        for (int off = 1; off < 8; off <<= 1) {
            int x = __shfl_up_sync(0xffffffffu, iv, off);
            if (lane >= off) iv += x;
        }
        if (lane == 7) s_total = iv;
        if (lane < 8) wsums[lane] = iv - v;
    }
    __syncthreads();
    int texc = exc + wsums[wid];

    // warp-parallel decoupled lookback (warp 0)
    if (wid == 0) {
        int total = s_total;
        if (bid == 0) {
            if (lane == 0) {
                atomicExch(&g_tstate[0], (2ULL << 32) | (unsigned)total);
                s_off = 0;
                if ((int)gridDim.x == 1) g_total = total;
            }
        } else {
            if (lane == 0) atomicExch(&g_tstate[bid], (1ULL << 32) | (unsigned)total);
            __syncwarp();
            long long off = 0;
            int j = bid - 1;
            while (1) {
                int idx = j - lane;
                unsigned long long st = 0;
                if (idx >= 0) {
                    do { st = atomicAdd(&g_tstate[idx], 0ULL); } while ((st >> 32) == 0ULL);
                }
                unsigned pmask = __ballot_sync(0xffffffffu, idx >= 0 && (st >> 32) == 2ULL);
                unsigned v;
                if (pmask) {
                    int l2 = __ffs(pmask) - 1;   // nearest inclusive-prefix
                    v = (lane <= l2) ? (unsigned)st : 0u;
                } else {
                    v = (idx >= 0) ? (unsigned)st : 0u;
                }
                #pragma unroll
                for (int o = 16; o; o >>= 1) v += __shfl_down_sync(0xffffffffu, v, o);
                v = __shfl_sync(0xffffffffu, v, 0);
                off += v;
                if (pmask || (j -= 32) < 0) break;
            }
            if (lane == 0) {
                atomicExch(&g_tstate[bid], (2ULL << 32) | (unsigned)(off + total));
                s_off = (int)off;
                if (bid == (int)gridDim.x - 1) g_total = (int)off + total;
            }
        }
    }
    __syncthreads();

    int run = s_off + texc;
    #pragma unroll
    for (int k = 0; k < 8; k++) {
        int i = i0 + k;
        if (i < N) {
            g_rankl[i] = run;
            if (fl[k]) {
                const float* src = pts + (size_t)i * 5;
                float* dst = qp + (size_t)run * 5;
                dst[0] = src[0]; dst[1] = src[1]; dst[2] = src[2];
                dst[3] = src[3]; dst[4] = src[4];
                run++;
            }
        }
    }
}

// ---------------- K6: sampled_points + idx + qp padding + state reset ----------------
__global__ void k_out(const float* __restrict__ pts, float* __restrict__ outp,
                      float* __restrict__ outi, float* __restrict__ qp, int M) {
    int t = blockIdx.x * blockDim.x + threadIdx.x;
    if (t < NTMAX) g_tstate[t] = 0ULL;   // reset for next replay
    if (t < M * S) {
        int m = t >> 5, j = t & 31;
        int c = g_scount[m];
        int p = g_sidx[t];
        bool msk = (j < c);
        outi[t] = msk ? (float)g_rankl[p] : 0.0f;
        #pragma unroll
        for (int cc = 0; cc < 5; cc++)
            outp[t * 5 + cc] = msk ? pts[p * 5 + cc] : 0.0f;
        if (t >= g_total) {
            #pragma unroll
            for (int cc = 0; cc < 5; cc++) qp[t * 5 + cc] = pts[cc];
        }
    }
}

// ---------------- launch ----------------
extern "C" void kernel_launch(void* const* d_in, const int* in_sizes, int n_in,
                              void* d_out, int out_size) {
    const float* pts   = (const float*)d_in[0];
    const float* boxes = (const float*)d_in[1];
    int N = in_sizes[0] / 5;
    int M = in_sizes[1] / 7;
    if (N > NMAX) N = NMAX;
    if (M > MMAX) M = MMAX;

    float* out  = (float*)d_out;
    float* outp = out;                            // sampled_points [M*S*5]
    float* outi = out + (size_t)M * S * 5;        // idx            [M*S]
    float* qp   = outi + (size_t)M * S;           // query_points   [M*S*5]

    int NT = (N + TILE - 1) / TILE;

    k_pack<<<(N + 1023) / 1024, 256>>>(pts, N);
    k_prefix<<<1, 1024>>>();
    k_fill<<<(N + 255) / 256, 256>>>(N);
    k_boxes<<<M, 256>>>(boxes, N);
    k_scan<<<NT, 256>>>(pts, qp, N);
    k_out<<<(M * S + 255) / 256, 256>>>(pts, outp, outi, qp, M);
}

// round 6
// speedup vs baseline: 7.0680x; 1.3575x over previous
#include <cuda_runtime.h>

#define S 32
#define NMAX 204800
#define MMAX 2048

#define GX 38
#define NC (GX * GX)
#define CELL 4.0f
#define ORG (-76.0f)
#define HITCAP 2048
#define TILE 2048
#define NTMAX 128

// ---------------- scratch (no allocations allowed) ----------------
__device__ float2 g_xy[NMAX];
__device__ int    g_flags[NMAX];
__device__ int    g_rankl[NMAX];
__device__ int    g_sidx[MMAX * S];
__device__ int    g_scount[MMAX];
__device__ int    g_cell[NMAX];      // packed: cell | (rank<<11)
__device__ int    g_chist[NC];
__device__ int    g_cstart[NC + 2];
__device__ float2 g_cxy[NMAX];
__device__ int    g_cidx[NMAX];
__device__ unsigned long long g_tstate[NTMAX];  // lookback: (status<<32)|sum
__device__ int    g_total;

__device__ __forceinline__ int cellc(float v) {
    int c = (int)floorf((v - ORG) * (1.0f / CELL));
    return min(max(c, 0), GX - 1);
}

// ---- warp-level sorted top-32 primitives (ascending) ----
__device__ __forceinline__ int warp_sort32(int v, int lane) {
    #pragma unroll
    for (int k = 2; k <= 32; k <<= 1) {
        #pragma unroll
        for (int j = k >> 1; j > 0; j >>= 1) {
            int o = __shfl_xor_sync(0xffffffffu, v, j);
            bool keepMin = (((lane & j) == 0) == ((lane & k) == 0));
            v = keepMin ? min(v, o) : max(v, o);
        }
    }
    return v;   // ascending across lanes
}
__device__ __forceinline__ int warp_bmerge32(int v, int lane) {
    #pragma unroll
    for (int j = 16; j > 0; j >>= 1) {
        int o = __shfl_xor_sync(0xffffffffu, v, j);
        v = ((lane & j) == 0) ? min(v, o) : max(v, o);
    }
    return v;   // bitonic -> ascending
}
// a, b sorted ascending; returns 32 smallest of union, ascending
__device__ __forceinline__ int warp_topk_merge(int a, int b, int lane) {
    int br = __shfl_sync(0xffffffffu, b, 31 - lane);
    return warp_bmerge32(min(a, br), lane);
}

// ---------------- K1: pack xy, clear flags, hierarchical histogram ----------------
__global__ void __launch_bounds__(256) k_pack(const float* __restrict__ pts, int N) {
    __shared__ int sh_cnt[NC];
    __shared__ int sh_base[NC];
    int t = threadIdx.x;
    for (int c = t; c < NC; c += 256) sh_cnt[c] = 0;
    __syncthreads();

    int i0 = (blockIdx.x * 256 + t) * 4;
    float2 P[4];
    int cell[4], lr[4];
    bool val[4];
    if (i0 + 4 <= N) {
        const float4* p4 = (const float4*)(pts + (size_t)i0 * 5);
        float4 v[5];
        #pragma unroll
        for (int k = 0; k < 5; k++) v[k] = p4[k];
        const float* f = (const float*)v;
        #pragma unroll
        for (int k = 0; k < 4; k++) { P[k] = make_float2(f[5 * k], f[5 * k + 1]); val[k] = true; }
    } else {
        #pragma unroll
        for (int k = 0; k < 4; k++) {
            int i = i0 + k;
            val[k] = (i < N);
            P[k] = val[k] ? make_float2(pts[i * 5], pts[i * 5 + 1]) : make_float2(0.f, 0.f);
        }
    }
    #pragma unroll
    for (int k = 0; k < 4; k++) {
        if (val[k]) {
            int i = i0 + k;
            g_xy[i] = P[k];
            g_flags[i] = 0;
            cell[k] = cellc(P[k].y) * GX + cellc(P[k].x);
            lr[k] = atomicAdd(&sh_cnt[cell[k]], 1);
        }
    }
    __syncthreads();
    for (int c = t; c < NC; c += 256) {
        int n = sh_cnt[c];
        sh_base[c] = n ? atomicAdd(&g_chist[c], n) : 0;
    }
    __syncthreads();
    #pragma unroll
    for (int k = 0; k < 4; k++)
        if (val[k]) g_cell[i0 + k] = cell[k] | ((sh_base[cell[k]] + lr[k]) << 11);
}

// ---------------- K2: exclusive prefix over cell histogram + reset hist ----------------
__global__ void __launch_bounds__(1024) k_prefix() {
    __shared__ int wofs[32];
    int tid = threadIdx.x, lane = tid & 31, wid = tid >> 5;
    int a = 0, b = 0;
    if (2 * tid < NC)     { a = g_chist[2 * tid];     g_chist[2 * tid] = 0; }
    if (2 * tid + 1 < NC) { b = g_chist[2 * tid + 1]; g_chist[2 * tid + 1] = 0; }
    int s = a + b;
    int inc = s;
    #pragma unroll
    for (int off = 1; off < 32; off <<= 1) {
        int v = __shfl_up_sync(0xffffffffu, inc, off);
        if (lane >= off) inc += v;
    }
    if (lane == 31) wofs[wid] = inc;
    __syncthreads();
    if (wid == 0) {
        int v = wofs[lane];
        int iv = v;
        #pragma unroll
        for (int off = 1; off < 32; off <<= 1) {
            int t2 = __shfl_up_sync(0xffffffffu, iv, off);
            if (lane >= off) iv += t2;
        }
        wofs[lane] = iv - v;
    }
    __syncthreads();
    int exc = inc - s + wofs[wid];
    if (2 * tid     <= NC + 1) g_cstart[2 * tid]     = exc;
    if (2 * tid + 1 <= NC + 1) g_cstart[2 * tid + 1] = exc + a;
}

// ---------------- K3: atomic-free scatter into cell lists ----------------
__global__ void __launch_bounds__(256) k_fill(int N) {
    int i = blockIdx.x * 256 + threadIdx.x;
    if (i < N) {
        int pc = g_cell[i];
        int pos = g_cstart[pc & 2047] + (pc >> 11);
        g_cxy[pos] = g_xy[i];
        g_cidx[pos] = i;
    }
}

// ---------------- K4: per-box selection via grid + warp top-32 ----------------
__global__ void __launch_bounds__(256) k_boxes(const float* __restrict__ boxes, int N) {
    int m = blockIdx.x;
    int tid = threadIdx.x;
    int lane = tid & 31, wid = tid >> 5;
    float bx = boxes[m * 7 + 0];
    float by = boxes[m * 7 + 1];
    float hx = __fmul_rn(boxes[m * 7 + 3], 0.5f);
    float hy = __fmul_rn(boxes[m * 7 + 4], 0.5f);
    float r  = __fmul_rn(sqrtf(__fadd_rn(__fmul_rn(hx, hx), __fmul_rn(hy, hy))), 1.1f);

    __shared__ int s_hit[HITCAP];
    __shared__ int s_ws[8][S];
    __shared__ int s_cnt, s_c;
    __shared__ int s_m[S], s_u[S];
    if (tid == 0) s_cnt = 0;
    __syncthreads();

    int cx0 = cellc(bx - r - 0.5f), cx1 = cellc(bx + r + 0.5f);
    int cy0 = cellc(by - r - 0.5f), cy1 = cellc(by + r + 0.5f);

    for (int cy = cy0; cy <= cy1; cy++) {
        int s0 = g_cstart[cy * GX + cx0];
        int s1 = g_cstart[cy * GX + cx1 + 1];
        for (int i = s0 + tid; i < s1; i += 256) {
            float2 p = g_cxy[i];
            float dx = __fadd_rn(bx, -p.x);
            float dy = __fadd_rn(by, -p.y);
            float d2 = __fadd_rn(__fmul_rn(dx, dx), __fmul_rn(dy, dy));
            if (sqrtf(d2) <= r) {
                int pos = atomicAdd(&s_cnt, 1);
                if (pos < HITCAP) s_hit[pos] = g_cidx[i];
            }
        }
    }
    __syncthreads();
    int cnt = s_cnt;

    if (cnt <= HITCAP) {
        // each warp: running sorted top-32 over its strided chunks (no barriers)
        int best = 0x7fffffff;
        bool first = true;
        for (int b = wid * 32; b < cnt; b += 256) {
            int idx = b + lane;
            int v = (idx < cnt) ? s_hit[idx] : 0x7fffffff;
            v = warp_sort32(v, lane);
            best = first ? v : warp_topk_merge(best, v, lane);
            first = false;
        }
        s_ws[wid][lane] = best;
        __syncthreads();
        if (wid == 0) {
            int acc = s_ws[0][lane];
            #pragma unroll
            for (int w = 1; w < 8; w++)
                acc = warp_topk_merge(acc, s_ws[w][lane], lane);
            int c = min(cnt, S);
            if (lane < c) s_m[lane] = acc;
            if (lane == 0) s_c = c;
        }
    } else {
        // overflow fallback: ordered warp scan for first 32 in-radius
        if (tid < 32) {
            int got = 0;
            for (int base = 0; got < S && base < N; base += 32) {
                int i = base + lane;
                bool mem = false;
                if (i < N) {
                    float2 p = g_xy[i];
                    float dx = __fadd_rn(bx, -p.x);
                    float dy = __fadd_rn(by, -p.y);
                    float d2 = __fadd_rn(__fmul_rn(dx, dx), __fmul_rn(dy, dy));
                    mem = (sqrtf(d2) <= r);
                }
                unsigned bmask = __ballot_sync(0xffffffffu, mem);
                int before = __popc(bmask & ((1u << lane) - 1));
                if (mem && got + before < S) s_m[got + before] = i;
                got += __popc(bmask);
            }
            if (lane == 0) s_c = S;
        }
    }
    __syncthreads();
    int c = s_c;

    if (c < S) {
        if (tid < 32) {
            int need = S - c;
            int got = 0;
            for (int base = 0; got < need && base < N; base += 32) {
                int i = base + lane;
                bool nm = false;
                if (i < N) {
                    float2 p = g_xy[i];
                    float dx = __fadd_rn(bx, -p.x);
                    float dy = __fadd_rn(by, -p.y);
                    float d2 = __fadd_rn(__fmul_rn(dx, dx), __fmul_rn(dy, dy));
                    nm = !(sqrtf(d2) <= r);
                }
                unsigned bmask = __ballot_sync(0xffffffffu, nm);
                int before = __popc(bmask & ((1u << lane) - 1));
                if (nm && got + before < need) s_u[got + before] = i;
                got += __popc(bmask);
            }
        }
        __syncthreads();
    }

    if (tid < S) {
        int v = (tid < c) ? s_m[tid] : s_u[tid - c];
        g_sidx[m * S + tid] = v;
        g_flags[v] = 1;   // benign race: all writers store 1
    }
    if (tid == 0) g_scount[m] = c;
}

// ---------------- K5: single-pass rank scan (warp-parallel lookback) + qp scatter ----------------
__global__ void __launch_bounds__(256) k_scan(const float* __restrict__ pts,
                                              float* __restrict__ qp, int N) {
    __shared__ int wsums[8];
    __shared__ int s_total;
    __shared__ int s_off;
    int bid = blockIdx.x, t = threadIdx.x, lane = t & 31, wid = t >> 5;
    int i0 = bid * TILE + t * 8;

    int fl[8];
    {
        const int4* fp = (const int4*)&g_flags[i0];
        int4 a = fp[0], b = fp[1];
        fl[0] = a.x; fl[1] = a.y; fl[2] = a.z; fl[3] = a.w;
        fl[4] = b.x; fl[5] = b.y; fl[6] = b.z; fl[7] = b.w;
    }
    int tsum = 0;
    #pragma unroll
    for (int k = 0; k < 8; k++) { if (i0 + k >= N) fl[k] = 0; tsum += fl[k]; }

    int inc = tsum;
    #pragma unroll
    for (int off = 1; off < 32; off <<= 1) {
        int v = __shfl_up_sync(0xffffffffu, inc, off);
        if (lane >= off) inc += v;
    }
    int exc = inc - tsum;
    if (lane == 31) wsums[wid] = inc;
    __syncthreads();
    if (wid == 0) {
        int v = (lane < 8) ? wsums[lane] : 0;
        int iv = v;
        #pragma unroll
        for (int off = 1; off < 8; off <<= 1) {
            int x = __shfl_up_sync(0xffffffffu, iv, off);
            if (lane >= off) iv += x;
        }
        if (lane == 7) s_total = iv;
        if (lane < 8) wsums[lane] = iv - v;
    }
    __syncthreads();
    int texc = exc + wsums[wid];

    if (wid == 0) {
        int total = s_total;
        if (bid == 0) {
            if (lane == 0) {
                atomicExch(&g_tstate[0], (2ULL << 32) | (unsigned)total);
                s_off = 0;
                if ((int)gridDim.x == 1) g_total = total;
            }
        } else {
            if (lane == 0) atomicExch(&g_tstate[bid], (1ULL << 32) | (unsigned)total);
            __syncwarp();
            long long off = 0;
            int j = bid - 1;
            while (1) {
                int idx = j - lane;
                unsigned long long st = 0;
                if (idx >= 0) {
                    do { st = atomicAdd(&g_tstate[idx], 0ULL); } while ((st >> 32) == 0ULL);
                }
                unsigned pmask = __ballot_sync(0xffffffffu, idx >= 0 && (st >> 32) == 2ULL);
                unsigned v;
                if (pmask) {
                    int l2 = __ffs(pmask) - 1;
                    v = (lane <= l2) ? (unsigned)st : 0u;
                } else {
                    v = (idx >= 0) ? (unsigned)st : 0u;
                }
                #pragma unroll
                for (int o = 16; o; o >>= 1) v += __shfl_down_sync(0xffffffffu, v, o);
                v = __shfl_sync(0xffffffffu, v, 0);
                off += v;
                if (pmask || (j -= 32) < 0) break;
            }
            if (lane == 0) {
                atomicExch(&g_tstate[bid], (2ULL << 32) | (unsigned)(off + total));
                s_off = (int)off;
                if (bid == (int)gridDim.x - 1) g_total = (int)off + total;
            }
        }
    }
    __syncthreads();

    int run = s_off + texc;
    #pragma unroll
    for (int k = 0; k < 8; k++) {
        int i = i0 + k;
        if (i < N) {
            g_rankl[i] = run;
            if (fl[k]) {
                const float* src = pts + (size_t)i * 5;
                float* dst = qp + (size_t)run * 5;
                dst[0] = src[0]; dst[1] = src[1]; dst[2] = src[2];
                dst[3] = src[3]; dst[4] = src[4];
                run++;
            }
        }
    }
}

// ---------------- K6: sampled_points + idx + qp padding + state reset ----------------
__global__ void k_out(const float* __restrict__ pts, float* __restrict__ outp,
                      float* __restrict__ outi, float* __restrict__ qp, int M) {
    int t = blockIdx.x * blockDim.x + threadIdx.x;
    if (t < NTMAX) g_tstate[t] = 0ULL;   // reset for next replay
    if (t < M * S) {
        int m = t >> 5, j = t & 31;
        int c = g_scount[m];
        int p = g_sidx[t];
        bool msk = (j < c);
        outi[t] = msk ? (float)g_rankl[p] : 0.0f;
        #pragma unroll
        for (int cc = 0; cc < 5; cc++)
            outp[t * 5 + cc] = msk ? pts[p * 5 + cc] : 0.0f;
        if (t >= g_total) {
            #pragma unroll
            for (int cc = 0; cc < 5; cc++) qp[t * 5 + cc] = pts[cc];
        }
    }
}

// ---------------- launch ----------------
extern "C" void kernel_launch(void* const* d_in, const int* in_sizes, int n_in,
                              void* d_out, int out_size) {
    const float* pts   = (const float*)d_in[0];
    const float* boxes = (const float*)d_in[1];
    int N = in_sizes[0] / 5;
    int M = in_sizes[1] / 7;
    if (N > NMAX) N = NMAX;
    if (M > MMAX) M = MMAX;

    float* out  = (float*)d_out;
    float* outp = out;                            // sampled_points [M*S*5]
    float* outi = out + (size_t)M * S * 5;        // idx            [M*S]
    float* qp   = outi + (size_t)M * S;           // query_points   [M*S*5]

    int NT = (N + TILE - 1) / TILE;

    k_pack<<<(N + 1023) / 1024, 256>>>(pts, N);
    k_prefix<<<1, 1024>>>();
    k_fill<<<(N + 255) / 256, 256>>>(N);
    k_boxes<<<M, 256>>>(boxes, N);
    k_scan<<<NT, 256>>>(pts, qp, N);
    k_out<<<(M * S + 255) / 256, 256>>>(pts, outp, outi, qp, M);
}